// round 6
// baseline (speedup 1.0000x reference)
#include <cuda_runtime.h>
#include <cuda_bf16.h>

// Problem constants
#define NB   64            // batch
#define CC   128           // channels
#define TT   300           // time
#define VV   25            // vertices
#define KK   3             // adjacency count
#define TV   (TT*VV)       // 7500
#define CO   (CC*KK)       // 384 output channels of 1x1 conv
#define NROWS (NB*TV)      // 480000 GEMM rows
#define NELEM (NB*CC*TT*VV) // 61,440,000 output elems
#define BN_EPS 1e-5f
#define NBLK2  (30*NB)     // aggregate grid blocks = 1920

// ---------------- packed f32x2 helpers (Blackwell FFMA2, PTX-only) ----------
typedef unsigned long long u64;

__device__ __forceinline__ u64 ffma2(u64 a, u64 b, u64 c) {
    u64 d;
    asm("fma.rn.f32x2 %0, %1, %2, %3;" : "=l"(d) : "l"(a), "l"(b), "l"(c));
    return d;
}
__device__ __forceinline__ u64 pack2(float lo, float hi) {
    u64 d;
    asm("mov.b64 %0, {%1, %2};" : "=l"(d) : "f"(lo), "f"(hi));
    return d;
}
__device__ __forceinline__ void unpack2(u64 v, float& lo, float& hi) {
    asm("mov.b64 {%0, %1}, %2;" : "=f"(lo), "=f"(hi) : "l"(v));
}

// ---------------- scratch (static device globals; no allocation allowed) ----
__device__ float g_y1[(size_t)NROWS * CO];   // intermediate conv output, [n,t,v,o]
__device__ float g_Wt[CC * CO];              // W transposed: [c][o]
__device__ float g_bias2[CC * VV];           // bias folded through A: [c][w]
__device__ float g_psum[NBLK2 * CC];         // per-block partial BN sums
__device__ float g_psq[NBLK2 * CC];
__device__ float g_scale[CC];
__device__ float g_shift[CC];

// ---------------- kernel 0: prep (transpose W, fold bias) -------------------
__global__ void prep_kernel(const float* __restrict__ W,
                            const float* __restrict__ b,
                            const float* __restrict__ A) {
    int tid = blockIdx.x * blockDim.x + threadIdx.x;
    int stride = gridDim.x * blockDim.x;
    // transpose W (CO x CC) -> Wt (CC x CO)
    for (int i = tid; i < CC * CO; i += stride) {
        int c = i / CO, o = i % CO;
        g_Wt[i] = W[o * CC + c];
    }
    // bias2[c][w] = sum_k b[k*CC+c] * sum_v A[k,v,w]
    for (int i = tid; i < CC * VV; i += stride) {
        int c = i / VV, w = i % VV;
        float s = 0.f;
        #pragma unroll
        for (int k = 0; k < KK; k++) {
            float cs = 0.f;
            #pragma unroll
            for (int v = 0; v < VV; v++) cs += A[k * VV * VV + v * VV + w];
            s += b[k * CC + c] * cs;
        }
        g_bias2[i] = s;
    }
}

// ---------------- kernel 1: SGEMM  y1[(n,t,v), o] = x[(n,t,v), c] @ Wt -----
// Block tile 128x128, K-step 8, 512 threads, 8x4 microtile per thread.
// Accumulators packed along ROWS (row-pair u64) so the A operand comes
// straight out of shared memory as 64-bit loads (no packing); only the 4
// B scalars per k-step get duplicated via mov.b64 (fits FFMA2 issue bubbles).
__global__ void __launch_bounds__(512) gemm1_kernel(const float* __restrict__ x) {
    const int o0 = blockIdx.x * 128;       // 0,128,256
    const int r0 = blockIdx.y * 128;       // row tile within one n (0..58)
    const int n  = blockIdx.z;

    __shared__ float Xs[8][128];
    __shared__ float Ws[8][128];

    const int tid = threadIdx.x;
    const int lkk = tid >> 6;              // 0..7
    const int li2 = (tid & 63) << 1;       // 0,2,...,126
    const int tx = tid & 31;               // col group: cols tx*4 .. tx*4+3
    const int ty = tid >> 5;               // 0..15, rows ty*8 .. ty*8+7

    const float* xn = x + (size_t)n * CC * TV;

    u64 acc2[4][4];   // [row-pair i][col j]; lo = row 2i, hi = row 2i+1
    #pragma unroll
    for (int i = 0; i < 4; i++)
        #pragma unroll
        for (int j = 0; j < 4; j++) acc2[i][j] = 0ull;

    for (int c0 = 0; c0 < CC; c0 += 8) {
        float2 xv = make_float2(0.f, 0.f);
        if (r0 + li2 < TV)
            xv = *(const float2*)(xn + (c0 + lkk) * TV + r0 + li2);
        *(float2*)&Xs[lkk][li2] = xv;
        *(float2*)&Ws[lkk][li2] = *(const float2*)(g_Wt + (c0 + lkk) * CO + o0 + li2);
        __syncthreads();

        #pragma unroll
        for (int kk = 0; kk < 8; kk++) {
            u64 a2[4];
            a2[0] = *(const u64*)&Xs[kk][ty * 8 + 0];
            a2[1] = *(const u64*)&Xs[kk][ty * 8 + 2];
            a2[2] = *(const u64*)&Xs[kk][ty * 8 + 4];
            a2[3] = *(const u64*)&Xs[kk][ty * 8 + 6];
            float4 bv = *(const float4*)&Ws[kk][tx * 4];
            u64 b2[4];
            b2[0] = pack2(bv.x, bv.x);
            b2[1] = pack2(bv.y, bv.y);
            b2[2] = pack2(bv.z, bv.z);
            b2[3] = pack2(bv.w, bv.w);
            #pragma unroll
            for (int i = 0; i < 4; i++)
                #pragma unroll
                for (int j = 0; j < 4; j++)
                    acc2[i][j] = ffma2(a2[i], b2[j], acc2[i][j]);
        }
        __syncthreads();
    }

    // epilogue: rows ty*8 + 2i (+1), cols o0 + tx*4 .. +3
    #pragma unroll
    for (int i = 0; i < 4; i++) {
        float lo[4], hi[4];
        #pragma unroll
        for (int j = 0; j < 4; j++) unpack2(acc2[i][j], lo[j], hi[j]);
        int r = r0 + ty * 8 + 2 * i;       // even; r<TV => r+1<TV (TV even)
        if (r < TV) {
            float* dst = g_y1 + (size_t)(n * TV + r) * CO + o0 + tx * 4;
            *(float4*)dst = *(float4*)lo;
            *(float4*)(dst + CO) = *(float4*)hi;
        }
    }
}

// ---------------- kernel 2: adjacency agg + bias + residual + relu + stats -
#define T_PER_BLK 10
#define AP 28   // padded A/bias row length (floats): 112B, keeps 8/16B alignment
__global__ void __launch_bounds__(128) aggregate_kernel(const float* __restrict__ x,
                                                        const float* __restrict__ A,
                                                        float* __restrict__ out) {
    const int n = blockIdx.y;
    const int tblk = blockIdx.x;
    const int c = threadIdx.x;   // channel

    __shared__ float A_s[KK * VV * AP];
    __shared__ float bias_s[CC * AP];

    // zero-fill padded regions, then load
    for (int i = c; i < KK * VV * AP; i += CC) A_s[i] = 0.f;
    for (int i = c; i < CC * AP; i += CC) bias_s[i] = 0.f;
    __syncthreads();
    for (int i = c; i < KK * VV * VV; i += CC) {
        int kv = i / VV, w = i % VV;
        A_s[kv * AP + w] = A[i];
    }
    for (int i = c; i < CC * VV; i += CC) {
        int ch = i / VV, w = i % VV;
        bias_s[ch * AP + w] = g_bias2[i];
    }
    __syncthreads();

    float bsum = 0.f, bsq = 0.f;

    for (int tt = 0; tt < T_PER_BLK; tt++) {
        const int t = tblk * T_PER_BLK + tt;
        u64 acc2[13];   // 26 packed accumulators (w=25 is zero padding)
        #pragma unroll
        for (int j = 0; j < 13; j++)
            acc2[j] = *(const u64*)&bias_s[c * AP + 2 * j];

        const float* yb = g_y1 + (size_t)((n * TT + t) * VV) * CO + c;
        #pragma unroll
        for (int k = 0; k < KK; k++) {
            #pragma unroll
            for (int v = 0; v < VV; v++) {
                float yv = yb[v * CO + k * CC];           // coalesced over c
                u64 yv2 = pack2(yv, yv);
                const u64* Ar2 = (const u64*)&A_s[(k * VV + v) * AP];
                #pragma unroll
                for (int j = 0; j < 13; j++)
                    acc2[j] = ffma2(yv2, Ar2[j], acc2[j]);
            }
        }

        // fused unpack + residual + relu + store + stats (no big temp array)
        const float* xr = x + (size_t)((n * CC + c) * TT + t) * VV;
        float* orow = out + (size_t)((n * CC + c) * TT + t) * VV;
        #pragma unroll
        for (int j = 0; j < 12; j++) {
            float lo, hi;
            unpack2(acc2[j], lo, hi);
            float y0 = fmaxf(lo + xr[2 * j], 0.f);
            float y1 = fmaxf(hi + xr[2 * j + 1], 0.f);
            orow[2 * j] = y0;
            orow[2 * j + 1] = y1;
            bsum += y0 + y1;
            bsq += y0 * y0 + y1 * y1;
        }
        {
            float lo, hi;
            unpack2(acc2[12], lo, hi);
            float y0 = fmaxf(lo + xr[24], 0.f);
            orow[24] = y0;
            bsum += y0;
            bsq += y0 * y0;
        }
    }
    // coalesced partial-sum write (no atomics)
    const int p = n * (TT / T_PER_BLK) + tblk;
    g_psum[p * CC + c] = bsum;
    g_psq[p * CC + c] = bsq;
}

// ---------------- kernel 3: reduce partials, fold BN into scale/shift ------
__global__ void __launch_bounds__(256) stats_kernel(const float* __restrict__ gamma,
                                                    const float* __restrict__ beta) {
    const int c = blockIdx.x;     // one block per channel
    const int tid = threadIdx.x;
    __shared__ float s1[256], s2[256];
    float a = 0.f, b2 = 0.f;
    for (int i = tid; i < NBLK2; i += 256) {
        a += g_psum[i * CC + c];
        b2 += g_psq[i * CC + c];
    }
    s1[tid] = a; s2[tid] = b2;
    __syncthreads();
    for (int s = 128; s > 0; s >>= 1) {
        if (tid < s) { s1[tid] += s1[tid + s]; s2[tid] += s2[tid + s]; }
        __syncthreads();
    }
    if (tid == 0) {
        const float inv = 1.f / (float)(NB * TT * VV);
        float mean = s1[0] * inv;
        float var = s2[0] * inv - mean * mean;
        float sc = gamma[c] * rsqrtf(var + BN_EPS);
        g_scale[c] = sc;
        g_shift[c] = beta[c] - mean * sc;
    }
}

// ---------------- kernel 4: in-place normalize + A passthrough tail --------
__global__ void normalize_kernel(float* __restrict__ out,
                                 const float* __restrict__ A,
                                 int out_size) {
    const int total4 = NELEM / 4;
    int stride = gridDim.x * blockDim.x;
    for (int idx = blockIdx.x * blockDim.x + threadIdx.x; idx < total4; idx += stride) {
        int e = idx * 4;
        int c = (e / TV) % CC;   // 4-aligned, TV%4==0 -> same c for all 4
        float sc = g_scale[c], sh = g_shift[c];
        float4 v = ((float4*)out)[idx];
        v.x = fmaf(v.x, sc, sh);
        v.y = fmaf(v.y, sc, sh);
        v.z = fmaf(v.z, sc, sh);
        v.w = fmaf(v.w, sc, sh);
        ((float4*)out)[idx] = v;
    }
    // reference returns (out, A): copy A into the tail if the harness expects it
    if (out_size > NELEM) {
        int tail = out_size - NELEM;  // expected KK*VV*VV = 1875
        for (int j = blockIdx.x * blockDim.x + threadIdx.x; j < tail && j < KK * VV * VV;
             j += stride)
            out[NELEM + j] = A[j];
    }
}

// ---------------- launch ----------------------------------------------------
extern "C" void kernel_launch(void* const* d_in, const int* in_sizes, int n_in,
                              void* d_out, int out_size) {
    const float* x     = (const float*)d_in[0];
    const float* A     = (const float*)d_in[1];
    const float* W     = (const float*)d_in[2];
    const float* b     = (const float*)d_in[3];
    const float* gamma = (const float*)d_in[4];
    const float* beta  = (const float*)d_in[5];
    float* out = (float*)d_out;

    prep_kernel<<<64, 256>>>(W, b, A);

    dim3 g1(CO / 128, (TV + 127) / 128, NB);   // (3, 59, 64)
    gemm1_kernel<<<g1, 512>>>(x);

    dim3 g2(TT / T_PER_BLK, NB);               // (30, 64)
    aggregate_kernel<<<g2, 128>>>(x, A, out);

    stats_kernel<<<CC, 256>>>(gamma, beta);

    normalize_kernel<<<2048, 256>>>(out, A, out_size);
}

// round 8
// speedup vs baseline: 1.0821x; 1.0821x over previous
#include <cuda_runtime.h>
#include <cuda_bf16.h>
#include <cstdint>

// Problem constants
#define NB   64            // batch
#define CC   128           // channels
#define TT   300           // time
#define VV   25            // vertices
#define KK   3             // adjacency count
#define TV   (TT*VV)       // 7500
#define CO   (CC*KK)       // 384 output channels of 1x1 conv
#define NROWS (NB*TV)      // 480000 GEMM rows
#define NELEM (NB*CC*TT*VV) // 61,440,000 output elems
#define BN_EPS 1e-5f
#define NBLK2  (30*NB)     // aggregate grid blocks = 1920
#define RPAD 7552          // 59*128, padded GEMM row count per n
#define KP 136             // padded k-dim of smem tiles (bf16 units)

typedef unsigned long long u64;

// ---------------- packed f32x2 helpers (kept for aggregate) -----------------
__device__ __forceinline__ u64 ffma2(u64 a, u64 b, u64 c) {
    u64 d;
    asm("fma.rn.f32x2 %0, %1, %2, %3;" : "=l"(d) : "l"(a), "l"(b), "l"(c));
    return d;
}
__device__ __forceinline__ u64 pack2(float lo, float hi) {
    u64 d;
    asm("mov.b64 %0, {%1, %2};" : "=l"(d) : "f"(lo), "f"(hi));
    return d;
}
__device__ __forceinline__ void unpack2(u64 v, float& lo, float& hi) {
    asm("mov.b64 {%0, %1}, %2;" : "=f"(lo), "=f"(hi) : "l"(v));
}

// ---------------- mma.sync helper (base PTX, works on plain sm_103) ---------
__device__ __forceinline__ void mma16816(float* c, const uint32_t* a, const uint32_t* b) {
    asm volatile(
        "mma.sync.aligned.m16n8k16.row.col.f32.bf16.bf16.f32 "
        "{%0,%1,%2,%3}, {%4,%5,%6,%7}, {%8,%9}, {%0,%1,%2,%3};"
        : "+f"(c[0]), "+f"(c[1]), "+f"(c[2]), "+f"(c[3])
        : "r"(a[0]), "r"(a[1]), "r"(a[2]), "r"(a[3]), "r"(b[0]), "r"(b[1]));
}

// ---------------- scratch (static device globals; no allocation allowed) ----
__device__ float g_y1[(size_t)NROWS * CO];                 // conv output [n,t,v,o]
__device__ __nv_bfloat16 g_xh[(size_t)NB * RPAD * CC];     // x transposed, bf16 hi
__device__ __nv_bfloat16 g_xl[(size_t)NB * RPAD * CC];     // x transposed, bf16 lo
__device__ __nv_bfloat16 g_Wh[CO * CC];                    // W bf16 hi ([o][c], k-contig)
__device__ __nv_bfloat16 g_Wl[CO * CC];                    // W bf16 lo
__device__ float g_bias2[CC * VV];                         // bias folded through A
__device__ float g_psum[NBLK2 * CC];
__device__ float g_psq[NBLK2 * CC];
__device__ float g_scale[CC];
__device__ float g_shift[CC];

// ---------------- kernel 0: prep (split W to bf16 hi/lo, fold bias) ---------
__global__ void prep_kernel(const float* __restrict__ W,
                            const float* __restrict__ b,
                            const float* __restrict__ A) {
    int tid = blockIdx.x * blockDim.x + threadIdx.x;
    int stride = gridDim.x * blockDim.x;
    for (int i = tid; i < CC * CO; i += stride) {
        float w = W[i];                       // W already [o][c] = K-contiguous
        __nv_bfloat16 hi = __float2bfloat16(w);
        g_Wh[i] = hi;
        g_Wl[i] = __float2bfloat16(w - __bfloat162float(hi));
    }
    for (int i = tid; i < CC * VV; i += stride) {
        int c = i / VV, w = i % VV;
        float s = 0.f;
        #pragma unroll
        for (int k = 0; k < KK; k++) {
            float cs = 0.f;
            #pragma unroll
            for (int v = 0; v < VV; v++) cs += A[k * VV * VV + v * VV + w];
            s += b[k * CC + c] * cs;
        }
        g_bias2[i] = s;
    }
}

// ---------------- kernel 1: transpose x [n,c,r] -> bf16 hi/lo [n,r,c] -------
__global__ void __launch_bounds__(256) transpose_split_kernel(const float* __restrict__ x) {
    __shared__ float tile[32][129];
    const int r0 = blockIdx.x * 128;
    const int c0 = blockIdx.y * 32;
    const int n  = blockIdx.z;
    const int tid = threadIdx.x;

    #pragma unroll
    for (int j = 0; j < 16; j++) {
        int e = tid + 256 * j;          // 4096 = 32c x 128r
        int cl = e >> 7, rl = e & 127;
        int rg = r0 + rl;
        float v = 0.f;
        if (rg < TV) v = x[((size_t)n * CC + c0 + cl) * TV + rg];
        tile[cl][rl] = v;
    }
    __syncthreads();
    #pragma unroll
    for (int j = 0; j < 16; j++) {
        int e = tid + 256 * j;
        int rl = e >> 5, cl = e & 31;
        float v = tile[cl][rl];
        __nv_bfloat16 hi = __float2bfloat16(v);
        size_t idx = ((size_t)n * RPAD + r0 + rl) * CC + c0 + cl;
        g_xh[idx] = hi;
        g_xl[idx] = __float2bfloat16(v - __bfloat162float(hi));
    }
}

// ---------------- kernel 2: bf16-pair mma.sync GEMM -------------------------
// Per CTA: 128 rows x all CO=384 (three 128-col o-passes).
// smem tiles [128][KP] bf16 (row-major, k contiguous): Ah, Al, Bh, Bl.
// 8 warps: wm = wid&1 (64 rows), wn = wid>>1 (32 cols). Per warp per k-step:
// 4 m-tiles x 4 n-tiles of m16n8k16, three products Ah*Bh + Al*Bh + Ah*Bl.
__device__ __forceinline__ void fill_tile(__nv_bfloat16* dst,
                                          const __nv_bfloat16* src, int tid) {
    #pragma unroll
    for (int i = 0; i < 8; i++) {
        int q = tid + 256 * i;          // 2048 chunks of 8 bf16
        int row = q >> 4, c8 = (q & 15) * 8;
        uint4 v = *(const uint4*)(src + (size_t)row * CC + c8);
        *(uint4*)(dst + row * KP + c8) = v;
    }
}

#define SMEM_TILE (128 * KP)                  // 17408 bf16 = 34816 B
#define SMEM_GEMM_TOTAL (4 * SMEM_TILE * 2)   // 139264 B

__global__ void __launch_bounds__(256) gemm_mma_kernel() {
    extern __shared__ __nv_bfloat16 smem[];
    __nv_bfloat16* sAh = smem;
    __nv_bfloat16* sAl = sAh + SMEM_TILE;
    __nv_bfloat16* sBh = sAl + SMEM_TILE;
    __nv_bfloat16* sBl = sBh + SMEM_TILE;

    const int r0 = blockIdx.x * 128;
    const int n  = blockIdx.y;
    const int tid = threadIdx.x;
    const int wid = tid >> 5, lane = tid & 31;
    const int wm = wid & 1, wn = wid >> 1;
    const int lr = lane >> 2;            // 0..7
    const int kq = (lane & 3) * 2;       // 0,2,4,6

    fill_tile(sAh, g_xh + ((size_t)n * RPAD + r0) * CC, tid);
    fill_tile(sAl, g_xl + ((size_t)n * RPAD + r0) * CC, tid);

    for (int o = 0; o < 3; o++) {
        __syncthreads();   // A visible (o=0) / previous pass finished (o>0)
        fill_tile(sBh, g_Wh + (size_t)(o * 128) * CC, tid);
        fill_tile(sBl, g_Wl + (size_t)(o * 128) * CC, tid);
        __syncthreads();

        float acc[4][4][4];
        #pragma unroll
        for (int mt = 0; mt < 4; mt++)
            #pragma unroll
            for (int nt = 0; nt < 4; nt++)
                #pragma unroll
                for (int j = 0; j < 4; j++) acc[mt][nt][j] = 0.f;

        #pragma unroll
        for (int kk = 0; kk < 8; kk++) {
            const int k0 = kk * 16 + kq;
            uint32_t ah[4][4], al[4][4], bh[4][2], bl[4][2];
            #pragma unroll
            for (int mt = 0; mt < 4; mt++) {
                int rm = wm * 64 + mt * 16 + lr;
                ah[mt][0] = *(const uint32_t*)(sAh + rm * KP + k0);
                ah[mt][1] = *(const uint32_t*)(sAh + (rm + 8) * KP + k0);
                ah[mt][2] = *(const uint32_t*)(sAh + rm * KP + k0 + 8);
                ah[mt][3] = *(const uint32_t*)(sAh + (rm + 8) * KP + k0 + 8);
                al[mt][0] = *(const uint32_t*)(sAl + rm * KP + k0);
                al[mt][1] = *(const uint32_t*)(sAl + (rm + 8) * KP + k0);
                al[mt][2] = *(const uint32_t*)(sAl + rm * KP + k0 + 8);
                al[mt][3] = *(const uint32_t*)(sAl + (rm + 8) * KP + k0 + 8);
            }
            #pragma unroll
            for (int nt = 0; nt < 4; nt++) {
                int rn = wn * 32 + nt * 8 + lr;
                bh[nt][0] = *(const uint32_t*)(sBh + rn * KP + k0);
                bh[nt][1] = *(const uint32_t*)(sBh + rn * KP + k0 + 8);
                bl[nt][0] = *(const uint32_t*)(sBl + rn * KP + k0);
                bl[nt][1] = *(const uint32_t*)(sBl + rn * KP + k0 + 8);
            }
            #pragma unroll
            for (int mt = 0; mt < 4; mt++)
                #pragma unroll
                for (int nt = 0; nt < 4; nt++) {
                    mma16816(acc[mt][nt], ah[mt], bh[nt]);
                    mma16816(acc[mt][nt], al[mt], bh[nt]);
                    mma16816(acc[mt][nt], ah[mt], bl[nt]);
                }
        }

        // epilogue: c0,c1 at (row, col..col+1); c2,c3 at (row+8, ...)
        #pragma unroll
        for (int mt = 0; mt < 4; mt++) {
            int row = r0 + wm * 64 + mt * 16 + lr;
            #pragma unroll
            for (int nt = 0; nt < 4; nt++) {
                int col = o * 128 + wn * 32 + nt * 8 + kq;
                if (row < TV) {
                    float2 v = make_float2(acc[mt][nt][0], acc[mt][nt][1]);
                    *(float2*)(g_y1 + ((size_t)(n * TV + row)) * CO + col) = v;
                }
                if (row + 8 < TV) {
                    float2 v = make_float2(acc[mt][nt][2], acc[mt][nt][3]);
                    *(float2*)(g_y1 + ((size_t)(n * TV + row + 8)) * CO + col) = v;
                }
            }
        }
    }
}

// ---------------- kernel 3: adjacency agg + bias + residual + relu + stats -
#define T_PER_BLK 10
#define AP 28
__global__ void __launch_bounds__(128) aggregate_kernel(const float* __restrict__ x,
                                                        const float* __restrict__ A,
                                                        float* __restrict__ out) {
    const int n = blockIdx.y;
    const int tblk = blockIdx.x;
    const int c = threadIdx.x;

    __shared__ float A_s[KK * VV * AP];
    __shared__ float bias_s[CC * AP];

    for (int i = c; i < KK * VV * AP; i += CC) A_s[i] = 0.f;
    for (int i = c; i < CC * AP; i += CC) bias_s[i] = 0.f;
    __syncthreads();
    for (int i = c; i < KK * VV * VV; i += CC) {
        int kv = i / VV, w = i % VV;
        A_s[kv * AP + w] = A[i];
    }
    for (int i = c; i < CC * VV; i += CC) {
        int ch = i / VV, w = i % VV;
        bias_s[ch * AP + w] = g_bias2[i];
    }
    __syncthreads();

    float bsum = 0.f, bsq = 0.f;

    for (int tt = 0; tt < T_PER_BLK; tt++) {
        const int t = tblk * T_PER_BLK + tt;
        u64 acc2[13];
        #pragma unroll
        for (int j = 0; j < 13; j++)
            acc2[j] = *(const u64*)&bias_s[c * AP + 2 * j];

        const float* yb = g_y1 + (size_t)((n * TT + t) * VV) * CO + c;
        #pragma unroll
        for (int k = 0; k < KK; k++) {
            #pragma unroll
            for (int v = 0; v < VV; v++) {
                float yv = yb[v * CO + k * CC];
                u64 yv2 = pack2(yv, yv);
                const u64* Ar2 = (const u64*)&A_s[(k * VV + v) * AP];
                #pragma unroll
                for (int j = 0; j < 13; j++)
                    acc2[j] = ffma2(yv2, Ar2[j], acc2[j]);
            }
        }

        const float* xr = x + (size_t)((n * CC + c) * TT + t) * VV;
        float* orow = out + (size_t)((n * CC + c) * TT + t) * VV;
        #pragma unroll
        for (int j = 0; j < 12; j++) {
            float lo, hi;
            unpack2(acc2[j], lo, hi);
            float y0 = fmaxf(lo + xr[2 * j], 0.f);
            float y1 = fmaxf(hi + xr[2 * j + 1], 0.f);
            orow[2 * j] = y0;
            orow[2 * j + 1] = y1;
            bsum += y0 + y1;
            bsq += y0 * y0 + y1 * y1;
        }
        {
            float lo, hi;
            unpack2(acc2[12], lo, hi);
            float y0 = fmaxf(lo + xr[24], 0.f);
            orow[24] = y0;
            bsum += y0;
            bsq += y0 * y0;
        }
    }
    const int p = n * (TT / T_PER_BLK) + tblk;
    g_psum[p * CC + c] = bsum;
    g_psq[p * CC + c] = bsq;
}

// ---------------- kernel 4: reduce partials, fold BN into scale/shift ------
__global__ void __launch_bounds__(256) stats_kernel(const float* __restrict__ gamma,
                                                    const float* __restrict__ beta) {
    const int c = blockIdx.x;
    const int tid = threadIdx.x;
    __shared__ float s1[256], s2[256];
    float a = 0.f, b2 = 0.f;
    for (int i = tid; i < NBLK2; i += 256) {
        a += g_psum[i * CC + c];
        b2 += g_psq[i * CC + c];
    }
    s1[tid] = a; s2[tid] = b2;
    __syncthreads();
    for (int s = 128; s > 0; s >>= 1) {
        if (tid < s) { s1[tid] += s1[tid + s]; s2[tid] += s2[tid + s]; }
        __syncthreads();
    }
    if (tid == 0) {
        const float inv = 1.f / (float)(NB * TT * VV);
        float mean = s1[0] * inv;
        float var = s2[0] * inv - mean * mean;
        float sc = gamma[c] * rsqrtf(var + BN_EPS);
        g_scale[c] = sc;
        g_shift[c] = beta[c] - mean * sc;
    }
}

// ---------------- kernel 5: in-place normalize + A passthrough tail --------
__global__ void normalize_kernel(float* __restrict__ out,
                                 const float* __restrict__ A,
                                 int out_size) {
    const int total4 = NELEM / 4;
    int stride = gridDim.x * blockDim.x;
    for (int idx = blockIdx.x * blockDim.x + threadIdx.x; idx < total4; idx += stride) {
        int e = idx * 4;
        int c = (e / TV) % CC;
        float sc = g_scale[c], sh = g_shift[c];
        float4 v = ((float4*)out)[idx];
        v.x = fmaf(v.x, sc, sh);
        v.y = fmaf(v.y, sc, sh);
        v.z = fmaf(v.z, sc, sh);
        v.w = fmaf(v.w, sc, sh);
        ((float4*)out)[idx] = v;
    }
    if (out_size > NELEM) {
        for (int j = blockIdx.x * blockDim.x + threadIdx.x;
             j < out_size - NELEM && j < KK * VV * VV; j += stride)
            out[NELEM + j] = A[j];
    }
}

// ---------------- launch ----------------------------------------------------
extern "C" void kernel_launch(void* const* d_in, const int* in_sizes, int n_in,
                              void* d_out, int out_size) {
    const float* x     = (const float*)d_in[0];
    const float* A     = (const float*)d_in[1];
    const float* W     = (const float*)d_in[2];
    const float* b     = (const float*)d_in[3];
    const float* gamma = (const float*)d_in[4];
    const float* beta  = (const float*)d_in[5];
    float* out = (float*)d_out;

    cudaFuncSetAttribute(gemm_mma_kernel,
                         cudaFuncAttributeMaxDynamicSharedMemorySize, SMEM_GEMM_TOTAL);

    prep_kernel<<<64, 256>>>(W, b, A);

    dim3 gt(RPAD / 128, CC / 32, NB);          // (59, 4, 64)
    transpose_split_kernel<<<gt, 256>>>(x);

    dim3 g1(RPAD / 128, NB);                   // (59, 64)
    gemm_mma_kernel<<<g1, 256, SMEM_GEMM_TOTAL>>>();

    dim3 g2(TT / T_PER_BLK, NB);               // (30, 64)
    aggregate_kernel<<<g2, 128>>>(x, A, out);

    stats_kernel<<<CC, 256>>>(gamma, beta);

    normalize_kernel<<<2048, 256>>>(out, A, out_size);
}

// round 9
// speedup vs baseline: 4.6308x; 4.2793x over previous
#include <cuda_runtime.h>
#include <cuda_fp16.h>
#include <cstdint>

// Problem constants
#define NB   64            // batch
#define CC   128           // channels
#define TT   300           // time
#define VV   25            // vertices
#define KK   3             // adjacency count
#define TV   (TT*VV)       // 7500
#define CO   (CC*KK)       // 384 output channels of 1x1 conv
#define NROWS (NB*TV)      // 480000 GEMM rows
#define NELEM (NB*CC*TT*VV) // 61,440,000 output elems
#define BN_EPS 1e-5f
#define RPAD 7552          // 59*128, padded GEMM row count per n
#define KP 136             // padded k-dim of smem tiles (fp16 units)
#define T_PER_BLK 5
#define NBLK2 ((TT/T_PER_BLK)*NB)   // 3840 aggregate blocks
#define AP 28              // padded A/bias row (floats)

typedef unsigned long long u64;

// ---------------- packed f32x2 helpers (aggregate inner product) ------------
__device__ __forceinline__ u64 ffma2(u64 a, u64 b, u64 c) {
    u64 d;
    asm("fma.rn.f32x2 %0, %1, %2, %3;" : "=l"(d) : "l"(a), "l"(b), "l"(c));
    return d;
}
__device__ __forceinline__ u64 pack2(float lo, float hi) {
    u64 d;
    asm("mov.b64 %0, {%1, %2};" : "=l"(d) : "f"(lo), "f"(hi));
    return d;
}
__device__ __forceinline__ void unpack2(u64 v, float& lo, float& hi) {
    asm("mov.b64 {%0, %1}, %2;" : "=f"(lo), "=f"(hi) : "l"(v));
}

// ---------------- fp16 mma.sync (base PTX, works on plain sm_103) -----------
__device__ __forceinline__ void mma16816(float* c, const uint32_t* a, const uint32_t* b) {
    asm volatile(
        "mma.sync.aligned.m16n8k16.row.col.f32.f16.f16.f32 "
        "{%0,%1,%2,%3}, {%4,%5,%6,%7}, {%8,%9}, {%0,%1,%2,%3};"
        : "+f"(c[0]), "+f"(c[1]), "+f"(c[2]), "+f"(c[3])
        : "r"(a[0]), "r"(a[1]), "r"(a[2]), "r"(a[3]), "r"(b[0]), "r"(b[1]));
}

// ---------------- scratch (static device globals; no allocation allowed) ----
__device__ float g_y1[(size_t)NROWS * CO];          // conv output [n,t,v,o]
__device__ __half g_xh[(size_t)NB * RPAD * CC];     // x transposed, fp16
__device__ __half g_Wh[CO * CC];                    // W fp16 ([o][c], k-contig)
__device__ float g_bias2[CC * VV];                  // bias folded through A
__device__ float g_psum[NBLK2 * CC];
__device__ float g_psq[NBLK2 * CC];
__device__ float g_scale[CC];
__device__ float g_shift[CC];

// ---------------- kernel 0: prep (W -> fp16, fold bias through A) -----------
__global__ void prep_kernel(const float* __restrict__ W,
                            const float* __restrict__ b,
                            const float* __restrict__ A) {
    int tid = blockIdx.x * blockDim.x + threadIdx.x;
    int stride = gridDim.x * blockDim.x;
    for (int i = tid; i < CC * CO; i += stride)
        g_Wh[i] = __float2half(W[i]);         // W already [o][c] = K-contiguous
    for (int i = tid; i < CC * VV; i += stride) {
        int c = i / VV, w = i % VV;
        float s = 0.f;
        #pragma unroll
        for (int k = 0; k < KK; k++) {
            float cs = 0.f;
            #pragma unroll
            for (int v = 0; v < VV; v++) cs += A[k * VV * VV + v * VV + w];
            s += b[k * CC + c] * cs;
        }
        g_bias2[i] = s;
    }
}

// ---------------- kernel 1: transpose x [n,c,r] -> fp16 [n,r,c] -------------
__global__ void __launch_bounds__(256) transpose_split_kernel(const float* __restrict__ x) {
    __shared__ float tile[32][129];
    const int r0 = blockIdx.x * 128;
    const int c0 = blockIdx.y * 32;
    const int n  = blockIdx.z;
    const int tid = threadIdx.x;

    #pragma unroll
    for (int j = 0; j < 16; j++) {
        int e = tid + 256 * j;          // 4096 = 32c x 128r
        int cl = e >> 7, rl = e & 127;
        int rg = r0 + rl;
        float v = 0.f;
        if (rg < TV) v = x[((size_t)n * CC + c0 + cl) * TV + rg];
        tile[cl][rl] = v;
    }
    __syncthreads();
    #pragma unroll
    for (int j = 0; j < 16; j++) {
        int e = tid + 256 * j;
        int rl = e >> 5, cl = e & 31;
        g_xh[((size_t)n * RPAD + r0 + rl) * CC + c0 + cl] = __float2half(tile[cl][rl]);
    }
}

// ---------------- kernel 2: fp16 single-product mma.sync GEMM ---------------
// Per CTA: 128 rows x all CO=384 (three 128-col o-passes).
// smem tiles [128][KP] fp16 (row-major, k contiguous): A, B.
// 8 warps: wm = wid&1 (64 rows), wn = wid>>1 (32 cols); 4x4 m16n8k16 per warp.
__device__ __forceinline__ void fill_tile(__half* dst, const __half* src, int tid) {
    #pragma unroll
    for (int i = 0; i < 8; i++) {
        int q = tid + 256 * i;          // 2048 chunks of 8 fp16
        int row = q >> 4, c8 = (q & 15) * 8;
        uint4 v = *(const uint4*)(src + (size_t)row * CC + c8);
        *(uint4*)(dst + row * KP + c8) = v;
    }
}

#define SMEM_TILE (128 * KP)                  // 17408 fp16 = 34816 B
#define SMEM_GEMM_TOTAL (2 * SMEM_TILE * 2)   // 69632 B

__global__ void __launch_bounds__(256) gemm_mma_kernel() {
    extern __shared__ __half smem_g[];
    __half* sA = smem_g;
    __half* sB = sA + SMEM_TILE;

    const int r0 = blockIdx.x * 128;
    const int n  = blockIdx.y;
    const int tid = threadIdx.x;
    const int wid = tid >> 5, lane = tid & 31;
    const int wm = wid & 1, wn = wid >> 1;
    const int lr = lane >> 2;            // 0..7
    const int kq = (lane & 3) * 2;       // 0,2,4,6

    fill_tile(sA, g_xh + ((size_t)n * RPAD + r0) * CC, tid);

    for (int o = 0; o < 3; o++) {
        __syncthreads();   // A visible (o=0) / previous pass done with sB (o>0)
        fill_tile(sB, g_Wh + (size_t)(o * 128) * CC, tid);
        __syncthreads();

        float acc[4][4][4];
        #pragma unroll
        for (int mt = 0; mt < 4; mt++)
            #pragma unroll
            for (int nt = 0; nt < 4; nt++)
                #pragma unroll
                for (int j = 0; j < 4; j++) acc[mt][nt][j] = 0.f;

        #pragma unroll
        for (int kk = 0; kk < 8; kk++) {
            const int k0 = kk * 16 + kq;
            uint32_t af[4][4], bf[4][2];
            #pragma unroll
            for (int mt = 0; mt < 4; mt++) {
                int rm = wm * 64 + mt * 16 + lr;
                af[mt][0] = *(const uint32_t*)(sA + rm * KP + k0);
                af[mt][1] = *(const uint32_t*)(sA + (rm + 8) * KP + k0);
                af[mt][2] = *(const uint32_t*)(sA + rm * KP + k0 + 8);
                af[mt][3] = *(const uint32_t*)(sA + (rm + 8) * KP + k0 + 8);
            }
            #pragma unroll
            for (int nt = 0; nt < 4; nt++) {
                int rn = wn * 32 + nt * 8 + lr;
                bf[nt][0] = *(const uint32_t*)(sB + rn * KP + k0);
                bf[nt][1] = *(const uint32_t*)(sB + rn * KP + k0 + 8);
            }
            #pragma unroll
            for (int mt = 0; mt < 4; mt++)
                #pragma unroll
                for (int nt = 0; nt < 4; nt++)
                    mma16816(acc[mt][nt], af[mt], bf[nt]);
        }

        // epilogue: c0,c1 at (row, col..col+1); c2,c3 at (row+8, ...)
        #pragma unroll
        for (int mt = 0; mt < 4; mt++) {
            int row = r0 + wm * 64 + mt * 16 + lr;
            #pragma unroll
            for (int nt = 0; nt < 4; nt++) {
                int col = o * 128 + wn * 32 + nt * 8 + kq;
                if (row < TV) {
                    float2 v = make_float2(acc[mt][nt][0], acc[mt][nt][1]);
                    *(float2*)(g_y1 + ((size_t)(n * TV + row)) * CO + col) = v;
                }
                if (row + 8 < TV) {
                    float2 v = make_float2(acc[mt][nt][2], acc[mt][nt][3]);
                    *(float2*)(g_y1 + ((size_t)(n * TV + row + 8)) * CO + col) = v;
                }
            }
        }
    }
}

// ---------------- kernel 3: adjacency agg + bias + residual + relu + stats -
// Per block: one n, 5 t, all 128 c. x residual and out go through a stride-129
// smem stage so global reads/writes are fully coalesced. y1 loads are batched
// (25 independent LDGs) before the FMA burst for high MLP.
#define STAGE_STRIDE 129
#define STAGE_FLOATS (128 * STAGE_STRIDE)            // 16512
#define SMEM_AGG_TOTAL ((STAGE_FLOATS + KK*VV*AP + CC*AP) * 4)   // 88784 B

__global__ void __launch_bounds__(128) aggregate_kernel(const float* __restrict__ x,
                                                        const float* __restrict__ A,
                                                        float* __restrict__ out) {
    extern __shared__ float smem_a[];
    float* stage  = smem_a;                       // [128][129]
    float* A_s    = stage + STAGE_FLOATS;         // [KK*VV][AP]
    float* bias_s = A_s + KK * VV * AP;           // [CC][AP]

    const int n = blockIdx.y;
    const int tblk = blockIdx.x;
    const int t0 = tblk * T_PER_BLK;
    const int c = threadIdx.x;

    for (int i = c; i < KK * VV * AP; i += CC) A_s[i] = 0.f;
    for (int i = c; i < CC * AP; i += CC) bias_s[i] = 0.f;
    __syncthreads();
    for (int i = c; i < KK * VV * VV; i += CC) {
        int kv = i / VV, w = i % VV;
        A_s[kv * AP + w] = A[i];
    }
    for (int i = c; i < CC * VV; i += CC) {
        int ch = i / VV, w = i % VV;
        bias_s[ch * AP + w] = g_bias2[i];
    }

    // cooperative coalesced load of x residual slice: 128 c x 125 (t,v) floats
    {
        const float* xb = x + ((size_t)n * CC) * TV + t0 * VV;
        for (int e = c; e < CC * (T_PER_BLK * VV); e += CC) {
            int row = e / (T_PER_BLK * VV);
            int off = e - row * (T_PER_BLK * VV);
            stage[row * STAGE_STRIDE + off] = xb[(size_t)row * TV + off];
        }
    }
    __syncthreads();

    float bsum = 0.f, bsq = 0.f;

    for (int tt = 0; tt < T_PER_BLK; tt++) {
        const int t = t0 + tt;
        u64 acc2[13];
        #pragma unroll
        for (int j = 0; j < 13; j++)
            acc2[j] = *(const u64*)&bias_s[c * AP + 2 * j];

        const float* yb = g_y1 + (size_t)((n * TT + t) * VV) * CO + c;
        #pragma unroll
        for (int k = 0; k < KK; k++) {
            float yv[VV];
            #pragma unroll
            for (int v = 0; v < VV; v++)
                yv[v] = yb[v * CO + k * CC];          // coalesced over c, 25-deep MLP
            #pragma unroll
            for (int v = 0; v < VV; v++) {
                u64 y2 = pack2(yv[v], yv[v]);
                const u64* Ar2 = (const u64*)&A_s[(k * VV + v) * AP];
                #pragma unroll
                for (int j = 0; j < 13; j++)
                    acc2[j] = ffma2(y2, Ar2[j], acc2[j]);
            }
        }

        // residual from stage, relu, write back into stage (same slots)
        float* srow = stage + c * STAGE_STRIDE + tt * VV;
        #pragma unroll
        for (int j = 0; j < 12; j++) {
            float lo, hi;
            unpack2(acc2[j], lo, hi);
            float y0 = fmaxf(lo + srow[2 * j], 0.f);
            float y1v = fmaxf(hi + srow[2 * j + 1], 0.f);
            srow[2 * j] = y0;
            srow[2 * j + 1] = y1v;
            bsum += y0 + y1v;
            bsq += y0 * y0 + y1v * y1v;
        }
        {
            float lo, hi;
            unpack2(acc2[12], lo, hi);
            float y0 = fmaxf(lo + srow[24], 0.f);
            srow[24] = y0;
            bsum += y0;
            bsq += y0 * y0;
        }
    }
    __syncthreads();

    // cooperative coalesced store to out
    {
        float* ob = out + ((size_t)n * CC) * TV + t0 * VV;
        for (int e = c; e < CC * (T_PER_BLK * VV); e += CC) {
            int row = e / (T_PER_BLK * VV);
            int off = e - row * (T_PER_BLK * VV);
            ob[(size_t)row * TV + off] = stage[row * STAGE_STRIDE + off];
        }
    }

    const int p = n * (TT / T_PER_BLK) + tblk;
    g_psum[p * CC + c] = bsum;
    g_psq[p * CC + c] = bsq;
}

// ---------------- kernel 4: reduce partials, fold BN into scale/shift ------
__global__ void __launch_bounds__(256) stats_kernel(const float* __restrict__ gamma,
                                                    const float* __restrict__ beta) {
    const int c = blockIdx.x;
    const int tid = threadIdx.x;
    __shared__ float s1[256], s2[256];
    float a = 0.f, b2 = 0.f;
    for (int i = tid; i < NBLK2; i += 256) {
        a += g_psum[i * CC + c];
        b2 += g_psq[i * CC + c];
    }
    s1[tid] = a; s2[tid] = b2;
    __syncthreads();
    for (int s = 128; s > 0; s >>= 1) {
        if (tid < s) { s1[tid] += s1[tid + s]; s2[tid] += s2[tid + s]; }
        __syncthreads();
    }
    if (tid == 0) {
        const float inv = 1.f / (float)(NB * TT * VV);
        float mean = s1[0] * inv;
        float var = s2[0] * inv - mean * mean;
        float sc = gamma[c] * rsqrtf(var + BN_EPS);
        g_scale[c] = sc;
        g_shift[c] = beta[c] - mean * sc;
    }
}

// ---------------- kernel 5: in-place normalize + A passthrough tail --------
__global__ void normalize_kernel(float* __restrict__ out,
                                 const float* __restrict__ A,
                                 int out_size) {
    const int total4 = NELEM / 4;
    int stride = gridDim.x * blockDim.x;
    for (int idx = blockIdx.x * blockDim.x + threadIdx.x; idx < total4; idx += stride) {
        int e = idx * 4;
        int c = (e / TV) % CC;
        float sc = g_scale[c], sh = g_shift[c];
        float4 v = ((float4*)out)[idx];
        v.x = fmaf(v.x, sc, sh);
        v.y = fmaf(v.y, sc, sh);
        v.z = fmaf(v.z, sc, sh);
        v.w = fmaf(v.w, sc, sh);
        ((float4*)out)[idx] = v;
    }
    if (out_size > NELEM) {
        for (int j = blockIdx.x * blockDim.x + threadIdx.x;
             j < out_size - NELEM && j < KK * VV * VV; j += stride)
            out[NELEM + j] = A[j];
    }
}

// ---------------- launch ----------------------------------------------------
extern "C" void kernel_launch(void* const* d_in, const int* in_sizes, int n_in,
                              void* d_out, int out_size) {
    const float* x     = (const float*)d_in[0];
    const float* A     = (const float*)d_in[1];
    const float* W     = (const float*)d_in[2];
    const float* b     = (const float*)d_in[3];
    const float* gamma = (const float*)d_in[4];
    const float* beta  = (const float*)d_in[5];
    float* out = (float*)d_out;

    cudaFuncSetAttribute(gemm_mma_kernel,
                         cudaFuncAttributeMaxDynamicSharedMemorySize, SMEM_GEMM_TOTAL);
    cudaFuncSetAttribute(aggregate_kernel,
                         cudaFuncAttributeMaxDynamicSharedMemorySize, SMEM_AGG_TOTAL);

    prep_kernel<<<64, 256>>>(W, b, A);

    dim3 gt(RPAD / 128, CC / 32, NB);          // (59, 4, 64)
    transpose_split_kernel<<<gt, 256>>>(x);

    dim3 g1(RPAD / 128, NB);                   // (59, 64)
    gemm_mma_kernel<<<g1, 256, SMEM_GEMM_TOTAL>>>();

    dim3 g2(TT / T_PER_BLK, NB);               // (60, 64)
    aggregate_kernel<<<g2, 128, SMEM_AGG_TOTAL>>>(x, A, out);

    stats_kernel<<<CC, 256>>>(gamma, beta);

    normalize_kernel<<<2048, 256>>>(out, A, out_size);
}